// round 1
// baseline (speedup 1.0000x reference)
#include <cuda_runtime.h>

typedef unsigned long long ull;

static constexpr int B = 32;
static constexpr int T = 32768;
static constexpr int H = 64;

// packed fp32x2 FMA: acc.lo += a.lo*b.lo ; acc.hi += a.hi*b.hi
__device__ __forceinline__ void fma2(ull& acc, ull a, ull b) {
    asm("fma.rn.f32x2 %0, %1, %2, %0;" : "+l"(acc) : "l"(a), "l"(b));
}
__device__ __forceinline__ float sum2(ull v) {
    float lo, hi;
    asm("mov.b64 {%0,%1}, %2;" : "=f"(lo), "=f"(hi) : "l"(v));
    return lo + hi;
}
__device__ __forceinline__ float sigf(float v) {
    float e = __expf(-v);                 // MUFU.EX2-based, ~1e-7 rel err
    return __fdividef(1.f, 1.f + e);      // MUFU.RCP-based
}
__device__ __forceinline__ float tanhf_fast(float v) {
    v = fminf(fmaxf(v, -15.f), 15.f);     // keep exp finite (avoid inf/inf)
    float e = __expf(-2.f * v);
    return __fdividef(1.f - e, 1.f + e);
}

// One CTA per batch sequence. 128 threads: pair (2i,2i+1) owns hidden element i;
// lane parity hk picks K-half [32*hk, 32*hk+32). Each thread holds 3 weight rows
// (r,z,n) x 32 cols packed as f32x2 in registers (96 regs). One barrier/step via
// double-buffered h in SMEM.
__global__ __launch_bounds__(128, 1)
void gru_kernel(const float* __restrict__ x,
                const float* __restrict__ w_ih,
                const float* __restrict__ w_hh,
                const float* __restrict__ b_ih,
                const float* __restrict__ b_hh,
                float* __restrict__ states)   // [B, T, H]
{
    // 68-float rows: odd half stored at +36 floats so the two broadcast groups
    // (even lanes read [0..31], odd lanes read [36..67]) hit disjoint banks.
    __shared__ float h_sh[2][68];

    const int bb  = blockIdx.x;
    const int tid = threadIdx.x;
    const int i   = tid >> 1;      // hidden element 0..63
    const int hk  = tid & 1;       // K-half

    // --- stationary weights in registers, packed as f32x2 pairs ---
    ull wr[16], wz[16], wn[16];
    {
        const ull* pr = (const ull*)(w_hh + (size_t)(i       ) * H + 32 * hk);
        const ull* pz = (const ull*)(w_hh + (size_t)(i +   64) * H + 32 * hk);
        const ull* pn = (const ull*)(w_hh + (size_t)(i +  128) * H + 32 * hk);
        #pragma unroll
        for (int m = 0; m < 16; m++) { wr[m] = pr[m]; wz[m] = pz[m]; wn[m] = pn[m]; }
    }
    const float wih_r = w_ih[i], wih_z = w_ih[i + 64], wih_n = w_ih[i + 128];
    const float bih_r = b_ih[i], bih_z = b_ih[i + 64], bih_n = b_ih[i + 128];
    const float bhh_r = b_hh[i], bhh_z = b_hh[i + 64], bhh_n = b_hh[i + 128];

    if (tid < 68) { h_sh[0][tid] = 0.f; h_sh[1][tid] = 0.f; }
    __syncthreads();

    const float* xb = x + (size_t)bb * T;
    float* sb = states + (size_t)bb * T * H + i;

    float h_prev = 0.f;
    int rb = 0;                                   // read buffer
    const int widx = (i < 32) ? i : (i + 4);      // padded write slot

    for (int t = 0; t < T; t++) {
        float x_t = __ldg(xb + t);                // broadcast, L1-resident line

        const ull* hv = (const ull*)&h_sh[rb][hk * 36];
        ull a0 = 0, a1 = 0, z0 = 0, z1 = 0, n0 = 0, n1 = 0;
        #pragma unroll
        for (int m = 0; m < 16; m += 2) {
            ull h0 = hv[m], h1 = hv[m + 1];
            fma2(a0, wr[m], h0); fma2(a1, wr[m + 1], h1);
            fma2(z0, wz[m], h0); fma2(z1, wz[m + 1], h1);
            fma2(n0, wn[m], h0); fma2(n1, wn[m + 1], h1);
        }
        float cr = sum2(a0) + sum2(a1);
        float cz = sum2(z0) + sum2(z1);
        float cn = sum2(n0) + sum2(n1);
        // combine K-halves across the lane pair (both lanes end with full sums)
        cr += __shfl_xor_sync(0xffffffffu, cr, 1);
        cz += __shfl_xor_sync(0xffffffffu, cz, 1);
        cn += __shfl_xor_sync(0xffffffffu, cn, 1);

        float r = sigf(cr + bhh_r + fmaf(x_t, wih_r, bih_r));
        float z = sigf(cz + bhh_z + fmaf(x_t, wih_z, bih_z));
        float n = tanhf_fast(fmaf(r, cn + bhh_n, fmaf(x_t, wih_n, bih_n)));
        float hnew = fmaf(z, h_prev - n, n);      // (1-z)*n + z*h
        h_prev = hnew;

        if (hk == 0) h_sh[rb ^ 1][widx] = hnew;   // publish h_{t+1}
        else         sb[(size_t)t * H] = hnew;    // stream state to GMEM
        rb ^= 1;
        __syncthreads();                          // single barrier per step
    }
}

// out[b,t] = dot(states[b,t,:], w_lin) + b_lin + x[b,t]  — parallel epilogue
__global__ __launch_bounds__(256)
void head_kernel(const float* __restrict__ x,
                 const float* __restrict__ states,
                 const float* __restrict__ w_lin,
                 const float* __restrict__ b_lin,
                 float* __restrict__ out)
{
    int idx = blockIdx.x * blockDim.x + threadIdx.x;   // 0 .. B*T-1 exactly
    const float4* s4 = (const float4*)(states + (size_t)idx * H);
    const float4* w4 = (const float4*)w_lin;
    float acc = 0.f;
    #pragma unroll
    for (int m = 0; m < 16; m++) {
        float4 s = __ldg(&s4[m]);
        float4 w = __ldg(&w4[m]);
        acc = fmaf(s.x, w.x, acc);
        acc = fmaf(s.y, w.y, acc);
        acc = fmaf(s.z, w.z, acc);
        acc = fmaf(s.w, w.w, acc);
    }
    out[idx] = acc + __ldg(b_lin) + __ldg(&x[idx]);
}

extern "C" void kernel_launch(void* const* d_in, const int* in_sizes, int n_in,
                              void* d_out, int out_size)
{
    const float* x     = (const float*)d_in[0];
    const float* w_ih  = (const float*)d_in[1];
    const float* w_hh  = (const float*)d_in[2];
    const float* b_ih  = (const float*)d_in[3];
    const float* b_hh  = (const float*)d_in[4];
    const float* w_lin = (const float*)d_in[5];
    const float* b_lin = (const float*)d_in[6];

    float* out    = (float*)d_out;                 // [B, T]
    float* states = out + (size_t)B * T;           // [B, T, H] follows in d_out

    gru_kernel<<<B, 128>>>(x, w_ih, w_hh, b_ih, b_hh, states);
    head_kernel<<<(B * T) / 256, 256>>>(x, states, w_lin, b_lin, out);
}